// round 4
// baseline (speedup 1.0000x reference)
#include <cuda_runtime.h>
#include <cuda_bf16.h>

#define TT 512
#define BB 32
#define VV 8000
#define LL 100
#define SS (2*LL+1)   // 201
#define NEGF (-1e30f)

#define NSCAN BB              // 32 consumer blocks (one per batch sample)
#define NPROD (TT*BB)         // 16384 producer blocks (one per row)
#define NBLK  (NSCAN + NPROD)

// Scratch (allocation-free rule: __device__ globals; zero-initialized at load)
__device__ float g_lp[TT*BB*SS];      // 13.2 MB
__device__ int   g_flags[TT*BB];      // row-ready flags (== epoch when ready)
__device__ int   g_epoch;

// 3-way logsumexp, MUFU-only fast path.
__device__ __forceinline__ float lse3(float a1, float a2, float a3) {
    float m = fmaxf(a1, fmaxf(a2, a3));
    float r = __expf(a1 - m) + __expf(a2 - m) + __expf(a3 - m);
    return m + __logf(r);
}

// ---------------------------------------------------------------------------
// K0: per-launch init (graph-replay safe: epoch increments, flags never reset)
// ---------------------------------------------------------------------------
__global__ void init_kernel(float* __restrict__ out) {
    g_epoch = g_epoch + 1;
    out[0] = 0.f;
}

// ---------------------------------------------------------------------------
// Fused kernel.
//   blocks [0, 32):        alpha-scan consumers (resident in wave 1, spin on flags)
//   blocks [32, 32+16384): producers, ONE ROW EACH (full occupancy across waves,
//                          never wait -> no deadlock; restores split-K1 bandwidth)
// ---------------------------------------------------------------------------
__global__ __launch_bounds__(256) void fused_kernel(const float* __restrict__ acts,
                                                    const int* __restrict__ targets,
                                                    const int* __restrict__ act_lens,
                                                    const int* __restrict__ label_lens,
                                                    float* __restrict__ out) {
    const int epoch = g_epoch;
    const int tid = threadIdx.x;

    if (blockIdx.x >= NSCAN) {
        // ================= PRODUCER: one row per block =================
        const int row = blockIdx.x - NSCAN;           // t*BB + b, t-major order
        const float* __restrict__ rowp = acts + (size_t)row * VV;
        const float4* __restrict__ p = (const float4*)rowp;
        __shared__ float sm[8], sv[8];
        __shared__ float sLogZ;

        float m = NEGF, s = 0.f;
        #pragma unroll 4
        for (int i = tid; i < VV/4; i += 256) {
            float4 v = p[i];
            float mx = fmaxf(fmaxf(v.x, v.y), fmaxf(v.z, v.w));
            if (mx > m) { s *= __expf(m - mx); m = mx; }
            s += __expf(v.x - m) + __expf(v.y - m) + __expf(v.z - m) + __expf(v.w - m);
        }
        #pragma unroll
        for (int off = 16; off; off >>= 1) {
            float m2 = __shfl_xor_sync(0xffffffffu, m, off);
            float s2 = __shfl_xor_sync(0xffffffffu, s, off);
            float M = fmaxf(m, m2);
            s = s * __expf(m - M) + s2 * __expf(m2 - M);
            m = M;
        }
        int w = tid >> 5;
        if ((tid & 31) == 0) { sm[w] = m; sv[w] = s; }
        __syncthreads();
        if (tid == 0) {
            float M = sm[0], Sv = sv[0];
            #pragma unroll
            for (int i = 1; i < 8; i++) {
                float m2 = sm[i], s2 = sv[i];
                float Mn = fmaxf(M, m2);
                Sv = Sv * __expf(M - Mn) + s2 * __expf(m2 - Mn);
                M = Mn;
            }
            sLogZ = M + __logf(Sv);
        }
        __syncthreads();

        // Gather the 201 extended-label emissions (row is L1-resident).
        if (tid < SS) {
            int b = row % BB;
            int lab = (tid & 1) ? __ldg(&targets[b*LL + (tid >> 1)]) : 0;
            g_lp[(size_t)row * SS + tid] = rowp[lab] - sLogZ;
        }
        __syncthreads();
        if (tid == 0) {
            __threadfence();                          // publish g_lp row
            g_flags[row] = epoch;                     // release flag
        }
    } else {
        // ================= SCAN (consumer) =================
        const int b = blockIdx.x;
        const int s = tid;                            // states 0..SS-1 live
        const int alen = act_lens[b];
        volatile int* vflags = g_flags;

        __shared__ float alpha[2][SS];

        bool cs = false;                              // can_skip for this state
        if (s < SS && (s & 1)) {
            int cur_lab = targets[b*LL + (s >> 1)];
            int prv_lab = (s >= 3) ? targets[b*LL + ((s - 2) >> 1)] : -1;
            cs = (cur_lab != 0) && (cur_lab != prv_lab);
        }

        // wait for rows t = 0..4 of this sample
        if (s == 0) {
            #pragma unroll
            for (int t = 0; t <= 4; t++)
                while (vflags[t*BB + b] != epoch) { }
            __threadfence();                          // acquire
        }
        __syncthreads();

        // init t = 0
        if (s < SS) {
            float a0 = NEGF;
            if (s <= 1) a0 = g_lp[(size_t)(0*BB + b)*SS + s];
            alpha[0][s] = a0;
        }

        // prefetch 4 time-steps of lp per thread
        float lpA[4], lpB[4];
        #pragma unroll
        for (int j = 0; j < 4; j++) {
            int t = 1 + j;
            lpA[j] = (s < SS) ? g_lp[(size_t)(t*BB + b)*SS + s] : 0.f;
        }
        __syncthreads();

        int cur = 1;                                  // buffer parity for t
        for (int t0 = 1; t0 < TT; t0 += 4) {
            // wait + prefetch rows t0+4 .. t0+7
            if (s == 0) {
                #pragma unroll
                for (int j = 0; j < 4; j++) {
                    int tn = t0 + 4 + j;
                    if (tn < TT)
                        while (vflags[tn*BB + b] != epoch) { }
                }
                __threadfence();                      // acquire
            }
            __syncthreads();
            #pragma unroll
            for (int j = 0; j < 4; j++) {
                int tn = t0 + 4 + j;
                lpB[j] = (s < SS && tn < TT) ? g_lp[(size_t)(tn*BB + b)*SS + s] : 0.f;
            }
            #pragma unroll
            for (int j = 0; j < 4; j++) {
                int t = t0 + j;
                if (t >= TT) break;                   // uniform across block
                int prv = cur ^ 1;
                if (s < SS) {
                    float a1 = alpha[prv][s];
                    float a2 = (s >= 1) ? alpha[prv][s - 1] : NEGF;
                    float a3 = (cs && s >= 2) ? alpha[prv][s - 2] : NEGF;
                    float nv = lse3(a1, a2, a3) + lpA[j];
                    alpha[cur][s] = (t < alen) ? nv : a1;
                }
                __syncthreads();
                cur ^= 1;
            }
            #pragma unroll
            for (int j = 0; j < 4; j++) lpA[j] = lpB[j];
        }

        if (s == 0) {
            int fin = cur ^ 1;                        // buffer holding alpha[T-1]
            int sl = 2 * label_lens[b];
            float a = alpha[fin][sl], c = alpha[fin][sl - 1];
            float m = fmaxf(a, c);
            float ll = m + __logf(__expf(a - m) + __expf(c - m));
            atomicAdd(out, -ll * (1.0f / (float)BB));
        }
    }
}

// ---------------------------------------------------------------------------
extern "C" void kernel_launch(void* const* d_in, const int* in_sizes, int n_in,
                              void* d_out, int out_size) {
    const float* acts       = (const float*)d_in[0];
    const int*   targets    = (const int*)d_in[1];
    const int*   act_lens   = (const int*)d_in[2];
    const int*   label_lens = (const int*)d_in[3];
    float* out = (float*)d_out;

    init_kernel<<<1, 1>>>(out);
    fused_kernel<<<NBLK, 256>>>(acts, targets, act_lens, label_lens, out);
}

// round 5
// speedup vs baseline: 1.0079x; 1.0079x over previous
#include <cuda_runtime.h>
#include <cuda_bf16.h>

#define TT 512
#define BB 32
#define VV 8000
#define LL 100
#define SS (2*LL+1)   // 201
#define NEGF (-1e30f)
#define WARPS 7
#define LOG2E 1.4426950408889634f
#define LN2   0.6931471805599453f

// Scratch (allocation-free rule: __device__ globals)
__device__ float g_lp[TT*BB*SS];      // 13.2 MB, log2-domain emissions

__device__ __forceinline__ float ex2f(float x) {
    float r; asm("ex2.approx.ftz.f32 %0, %1;" : "=f"(r) : "f"(x)); return r;
}
__device__ __forceinline__ float lg2f(float x) {
    float r; asm("lg2.approx.ftz.f32 %0, %1;" : "=f"(r) : "f"(x)); return r;
}

// ---------------------------------------------------------------------------
// K1: logZ = logsumexp over V of acts[t,b,:], then gather lp_ext for this row
//     (row L1-resident), stored in LOG2 domain. One block per (t,b) row.
// ---------------------------------------------------------------------------
__global__ __launch_bounds__(256) void logz_gather_kernel(const float* __restrict__ acts,
                                                          const int* __restrict__ targets,
                                                          float* __restrict__ out) {
    const int row = blockIdx.x;                    // t*BB + b
    const int b   = row % BB;
    const float* __restrict__ rowp = acts + (size_t)row * VV;
    const float4* __restrict__ p = (const float4*)rowp;
    const int tid = threadIdx.x;

    if (row == 0 && tid == 0) out[0] = 0.f;        // zero the batch-mean accumulator

    float m = NEGF, s = 0.f;
    #pragma unroll 4
    for (int i = tid; i < VV/4; i += 256) {
        float4 v = p[i];
        float mx = fmaxf(fmaxf(v.x, v.y), fmaxf(v.z, v.w));
        if (mx > m) { s *= __expf(m - mx); m = mx; }
        s += __expf(v.x - m) + __expf(v.y - m) + __expf(v.z - m) + __expf(v.w - m);
    }
    #pragma unroll
    for (int off = 16; off; off >>= 1) {
        float m2 = __shfl_xor_sync(0xffffffffu, m, off);
        float s2 = __shfl_xor_sync(0xffffffffu, s, off);
        float M = fmaxf(m, m2);
        s = s * __expf(m - M) + s2 * __expf(m2 - M);
        m = M;
    }
    __shared__ float sm[8], sv[8];
    __shared__ float sLogZ;
    int w = tid >> 5;
    if ((tid & 31) == 0) { sm[w] = m; sv[w] = s; }
    __syncthreads();
    if (tid == 0) {
        float M = sm[0], Sv = sv[0];
        #pragma unroll
        for (int i = 1; i < 8; i++) {
            float m2 = sm[i], s2 = sv[i];
            float Mn = fmaxf(M, m2);
            Sv = Sv * __expf(M - Mn) + s2 * __expf(m2 - Mn);
            M = Mn;
        }
        sLogZ = M + __logf(Sv);
    }
    __syncthreads();

    // Gather 201 extended-label emissions (L1 hits), scale to log2 domain.
    if (tid < SS) {
        int lab = (tid & 1) ? __ldg(&targets[b*LL + (tid >> 1)]) : 0;
        g_lp[(size_t)row * SS + tid] = (rowp[lab] - sLogZ) * LOG2E;
    }
}

// ---------------------------------------------------------------------------
// K2: skewed-warp alpha scan. One block per sample, 7 warps, thread = state.
//     No __syncthreads in the time loop: cross-warp boundary values flow
//     through a write-once smem ring (atomic STS.64; sentinel = "not ready").
// ---------------------------------------------------------------------------
__global__ __launch_bounds__(224) void scan_kernel(const int* __restrict__ targets,
                                                   const int* __restrict__ act_lens,
                                                   const int* __restrict__ label_lens,
                                                   float* __restrict__ out) {
    const int b = blockIdx.x;
    const int tid = threadIdx.x;
    const int w = tid >> 5;
    const int l = tid & 31;
    const int s = tid;                         // state id; live if s < SS
    const bool live = (s < SS);
    const int alen = act_lens[b];
    const unsigned long long SENT = 0x7F7F7F7F7F7F7F7FULL;  // ~3.39e38 pair: unreachable

    __shared__ unsigned long long bnd[WARPS][TT];   // 28 KB boundary ring
    __shared__ float fin[224];

    for (int i = tid; i < WARPS*TT; i += 224)
        ((unsigned long long*)bnd)[i] = SENT;

    bool cs = false;                           // can_skip (odd states only)
    if (live && (s & 1)) {
        int cl = targets[b*LL + (s >> 1)];
        int pl = (s >= 3) ? targets[b*LL + ((s - 2) >> 1)] : -1;
        cs = (cl != 0) && (cl != pl);
    }
    __syncthreads();                           // sentinel init visible

    // t = 0
    float a = NEGF;
    if (s <= 1) a = g_lp[(size_t)b * SS + s];
    {
        float a30 = __shfl_sync(0xffffffffu, a, 30);
        if (l == 31) {
            unsigned long long pk = ((unsigned long long)__float_as_uint(a) << 32)
                                    | __float_as_uint(a30);
            *((volatile unsigned long long*)&bnd[w][0]) = pk;
        }
    }

    // per-thread lp prefetch, 8 steps deep
    float lpr[8];
    #pragma unroll
    for (int j = 0; j < 8; j++) {
        int t = 1 + j;
        lpr[j] = (live && t < TT) ? g_lp[(size_t)(t*BB + b)*SS + s] : 0.f;
    }

    for (int t0 = 1; t0 < TT; t0 += 8) {
        #pragma unroll
        for (int j = 0; j < 8; j++) {
            int t = t0 + j;
            if (t >= TT) break;                // uniform
            float lp_t = lpr[j];
            int tp = t + 8;
            lpr[j] = (live && tp < TT) ? g_lp[(size_t)(tp*BB + b)*SS + s] : 0.f;

            // cross-warp boundary: states 32w-2 (bx), 32w-1 (by) at time t-1
            float bx = NEGF, by = NEGF;
            if (w > 0 && l < 2) {
                unsigned long long v;
                do { v = *((volatile unsigned long long*)&bnd[w-1][t-1]); }
                while (v == SENT);
                bx = __uint_as_float((unsigned int)v);
                by = __uint_as_float((unsigned int)(v >> 32));
            }
            float a2 = __shfl_up_sync(0xffffffffu, a, 1);
            float a3 = __shfl_up_sync(0xffffffffu, a, 2);
            if (l == 0) { a2 = by; a3 = bx; }  // w==0: by=bx=NEGF already
            if (l == 1) { a3 = by; }

            float a1 = a;
            float a3e = cs ? a3 : NEGF;
            float m = fmaxf(a1, fmaxf(a2, a3e));
            float r = ex2f(a1 - m) + ex2f(a2 - m) + ex2f(a3e - m);
            float nv = m + lg2f(r) + lp_t;
            a = (t < alen) ? nv : a1;

            float a30 = __shfl_sync(0xffffffffu, a, 30);
            if (l == 31) {
                unsigned long long pk = ((unsigned long long)__float_as_uint(a) << 32)
                                        | __float_as_uint(a30);
                *((volatile unsigned long long*)&bnd[w][t]) = pk;
            }
        }
    }

    fin[tid] = a;
    __syncthreads();
    if (tid == 0) {
        int sl = 2 * label_lens[b];
        float x = fin[sl], y = fin[sl - 1];
        float m = fmaxf(x, y);
        float ll2 = m + lg2f(ex2f(x - m) + ex2f(y - m));   // log2 domain
        atomicAdd(out, -ll2 * (LN2 / (float)BB));
    }
}

// ---------------------------------------------------------------------------
extern "C" void kernel_launch(void* const* d_in, const int* in_sizes, int n_in,
                              void* d_out, int out_size) {
    const float* acts       = (const float*)d_in[0];
    const int*   targets    = (const int*)d_in[1];
    const int*   act_lens   = (const int*)d_in[2];
    const int*   label_lens = (const int*)d_in[3];
    float* out = (float*)d_out;

    logz_gather_kernel<<<TT*BB, 256>>>(acts, targets, out);
    scan_kernel<<<BB, 224>>>(targets, act_lens, label_lens, out);
}

// round 6
// speedup vs baseline: 1.2365x; 1.2268x over previous
#include <cuda_runtime.h>
#include <cuda_bf16.h>

#define TT 512
#define BB 32
#define VV 8000
#define LL 100
#define SS (2*LL+1)   // 201
#define NEGF (-1e30f)
#define LOG2E 1.4426950408889634f
#define LN2   0.6931471805599453f

#define SWARPS 8      // scan warps per sample
#define OWN   28      // owned states per warp (lanes 4..31)
#define DEPTH 4       // lp prefetch depth (pairs)

// Scratch (allocation-free rule: __device__ globals)
__device__ float g_lp[TT*BB*SS];      // 13.2 MB, log2-domain emissions

__device__ __forceinline__ float ex2f(float x) {
    float r; asm("ex2.approx.ftz.f32 %0, %1;" : "=f"(r) : "f"(x)); return r;
}
__device__ __forceinline__ float lg2f(float x) {
    float r; asm("lg2.approx.ftz.f32 %0, %1;" : "=f"(r) : "f"(x)); return r;
}

// ---------------------------------------------------------------------------
// K1: logZ = logsumexp over V of acts[t,b,:], then gather lp_ext for this row
//     (row L1-resident), stored in LOG2 domain. One block per (t,b) row.
// ---------------------------------------------------------------------------
__global__ __launch_bounds__(256) void logz_gather_kernel(const float* __restrict__ acts,
                                                          const int* __restrict__ targets,
                                                          float* __restrict__ out) {
    const int row = blockIdx.x;                    // t*BB + b
    const int b   = row % BB;
    const float* __restrict__ rowp = acts + (size_t)row * VV;
    const float4* __restrict__ p = (const float4*)rowp;
    const int tid = threadIdx.x;

    if (row == 0 && tid == 0) out[0] = 0.f;        // zero the batch-mean accumulator

    float m = NEGF, s = 0.f;
    #pragma unroll 4
    for (int i = tid; i < VV/4; i += 256) {
        float4 v = p[i];
        float mx = fmaxf(fmaxf(v.x, v.y), fmaxf(v.z, v.w));
        if (mx > m) { s *= __expf(m - mx); m = mx; }
        s += __expf(v.x - m) + __expf(v.y - m) + __expf(v.z - m) + __expf(v.w - m);
    }
    #pragma unroll
    for (int off = 16; off; off >>= 1) {
        float m2 = __shfl_xor_sync(0xffffffffu, m, off);
        float s2 = __shfl_xor_sync(0xffffffffu, s, off);
        float M = fmaxf(m, m2);
        s = s * __expf(m - M) + s2 * __expf(m2 - M);
        m = M;
    }
    __shared__ float sm[8], sv[8];
    __shared__ float sLogZ;
    int w = tid >> 5;
    if ((tid & 31) == 0) { sm[w] = m; sv[w] = s; }
    __syncthreads();
    if (tid == 0) {
        float M = sm[0], Sv = sv[0];
        #pragma unroll
        for (int i = 1; i < 8; i++) {
            float m2 = sm[i], s2 = sv[i];
            float Mn = fmaxf(M, m2);
            Sv = Sv * __expf(M - Mn) + s2 * __expf(m2 - Mn);
            M = Mn;
        }
        sLogZ = M + __logf(Sv);
    }
    __syncthreads();

    // Gather 201 extended-label emissions (L1 hits), scale to log2 domain.
    if (tid < SS) {
        int lab = (tid & 1) ? __ldg(&targets[b*LL + (tid >> 1)]) : 0;
        g_lp[(size_t)row * SS + tid] = (rowp[lab] - sLogZ) * LOG2E;
    }
}

// ---------------------------------------------------------------------------
// K2: alpha scan, TWO time-steps per barrier.
//     Warp w: lanes 4..31 own states 28w..28w+27; lanes 0..3 mirror the
//     previous warp's top 4 states (refreshed from a tiny smem boundary
//     buffer, double-buffered -> one __syncthreads per 2 steps).
// ---------------------------------------------------------------------------
__global__ __launch_bounds__(32*SWARPS) void scan_kernel(const int* __restrict__ targets,
                                                         const int* __restrict__ act_lens,
                                                         const int* __restrict__ label_lens,
                                                         float* __restrict__ out) {
    const int b   = blockIdx.x;
    const int tid = threadIdx.x;
    const int w   = tid >> 5;
    const int l   = tid & 31;
    const int s   = OWN * w + l - 4;           // state id (mirrors for l<4)
    const bool live = (s >= 0 && s < SS);
    const bool owned = (l >= 4) && live;
    const int alen = act_lens[b];

    __shared__ float bnd[2][SWARPS*4];         // boundary states, double-buffered
    __shared__ float fin[SS];

    bool cs = false;                           // can_skip (odd states only)
    if (live && (s & 1)) {
        int cl = targets[b*LL + (s >> 1)];
        int pl = (s >= 3) ? targets[b*LL + ((s - 2) >> 1)] : -1;
        cs = (cl != 0) && (cl != pl);
    }

    // alpha[0]
    float a = NEGF;
    if (live && s <= 1) a = g_lp[(size_t)b * SS + s];

    // lp prefetch: DEPTH pairs ahead. Pair p covers t = 1+2p, 2+2p.
    float lt[DEPTH], lt1[DEPTH];
    #pragma unroll
    for (int j = 0; j < DEPTH; j++) {
        int t = 1 + 2*j;
        lt[j]  = live ? g_lp[(size_t)(t*BB + b)*SS + s]     : 0.f;
        lt1[j] = live ? g_lp[(size_t)((t+1)*BB + b)*SS + s] : 0.f;
    }
    __syncthreads();

    const int NPAIR = (TT - 2) / 2;            // 255 pairs: t = 1..510
    for (int p = 0; p < NPAIR; p++) {
        const int t = 1 + 2*p;
        float lp_t  = lt[p & (DEPTH-1)];
        float lp_t1 = lt1[p & (DEPTH-1)];
        {   // refill slot for pair p+DEPTH
            int tf = 1 + 2*(p + DEPTH);
            bool ok = live && (tf < TT - 1);
            lt [p & (DEPTH-1)] = ok ? g_lp[(size_t)(tf*BB + b)*SS + s]     : 0.f;
            lt1[p & (DEPTH-1)] = ok ? g_lp[(size_t)((tf+1)*BB + b)*SS + s] : 0.f;
        }

        // ---- step A: c = alpha[t][s]  (valid for lanes >= 2)
        float a2 = __shfl_up_sync(0xffffffffu, a, 1);
        float a3 = __shfl_up_sync(0xffffffffu, a, 2);
        float c;
        {
            float a3e = cs ? a3 : NEGF;
            float m = fmaxf(a, fmaxf(a2, a3e));
            float r = ex2f(a - m) + ex2f(a2 - m) + ex2f(a3e - m);
            c = m + lg2f(r) + lp_t;
        }
        c = (t < alen) ? c : a;
        if (!live) c = NEGF;

        // ---- step B: nv = alpha[t+1][s]  (valid for lanes >= 4)
        float c2 = __shfl_up_sync(0xffffffffu, c, 1);
        float c3 = __shfl_up_sync(0xffffffffu, c, 2);
        float nv;
        {
            float c3e = cs ? c3 : NEGF;
            float m = fmaxf(c, fmaxf(c2, c3e));
            float r = ex2f(c - m) + ex2f(c2 - m) + ex2f(c3e - m);
            nv = m + lg2f(r) + lp_t1;
        }
        nv = (t + 1 < alen) ? nv : c;
        if (!live) nv = NEGF;

        // ---- boundary exchange (one barrier per 2 steps)
        if (l >= 28) bnd[p & 1][w*4 + (l - 28)] = nv;   // states 28w+24..28w+27
        __syncthreads();
        if (l < 4) a = (w > 0) ? bnd[p & 1][(w - 1)*4 + l] : NEGF;
        else       a = nv;
    }

    // ---- tail: single step t = TT-1 = 511
    {
        const int t = TT - 1;
        float lp_t = live ? g_lp[(size_t)(t*BB + b)*SS + s] : 0.f;
        float a2 = __shfl_up_sync(0xffffffffu, a, 1);
        float a3 = __shfl_up_sync(0xffffffffu, a, 2);
        float a3e = cs ? a3 : NEGF;
        float m = fmaxf(a, fmaxf(a2, a3e));
        float r = ex2f(a - m) + ex2f(a2 - m) + ex2f(a3e - m);
        float c = m + lg2f(r) + lp_t;
        a = (t < alen) ? c : a;
    }

    if (owned) fin[s] = a;
    __syncthreads();
    if (tid == 0) {
        int sl = 2 * label_lens[b];
        float x = fin[sl], y = fin[sl - 1];
        float m = fmaxf(x, y);
        float ll2 = m + lg2f(ex2f(x - m) + ex2f(y - m));   // log2 domain
        atomicAdd(out, -ll2 * (LN2 / (float)BB));
    }
}

// ---------------------------------------------------------------------------
extern "C" void kernel_launch(void* const* d_in, const int* in_sizes, int n_in,
                              void* d_out, int out_size) {
    const float* acts       = (const float*)d_in[0];
    const int*   targets    = (const int*)d_in[1];
    const int*   act_lens   = (const int*)d_in[2];
    const int*   label_lens = (const int*)d_in[3];
    float* out = (float*)d_out;

    logz_gather_kernel<<<TT*BB, 256>>>(acts, targets, out);
    scan_kernel<<<BB, 32*SWARPS>>>(targets, act_lens, label_lens, out);
}

// round 7
// speedup vs baseline: 2.3484x; 1.8992x over previous
#include <cuda_runtime.h>
#include <cuda_bf16.h>

#define TT 512
#define BB 32
#define VV 8000
#define LL 100
#define SS (2*LL+1)   // 201
#define NEGF (-1e30f)
#define LOG2E 1.4426950408889634f
#define LN2   0.6931471805599453f

#define SWARPS 8      // scan warps per sample
#define OWN   28      // owned states per warp (lanes 4..31)
#define DEPTH 4       // lp prefetch depth (pairs) -- MUST stay compile-time indexed

// Scratch (allocation-free rule: __device__ globals)
__device__ float g_lp[TT*BB*SS];      // 13.2 MB, log2-domain emissions

__device__ __forceinline__ float ex2f(float x) {
    float r; asm("ex2.approx.ftz.f32 %0, %1;" : "=f"(r) : "f"(x)); return r;
}
__device__ __forceinline__ float lg2f(float x) {
    float r; asm("lg2.approx.ftz.f32 %0, %1;" : "=f"(r) : "f"(x)); return r;
}

// ---------------------------------------------------------------------------
// K1: logZ = logsumexp over V of acts[t,b,:], then gather lp_ext for this row
//     (row L1-resident), stored in LOG2 domain. One block per (t,b) row.
// ---------------------------------------------------------------------------
__global__ __launch_bounds__(256) void logz_gather_kernel(const float* __restrict__ acts,
                                                          const int* __restrict__ targets,
                                                          float* __restrict__ out) {
    const int row = blockIdx.x;                    // t*BB + b
    const int b   = row % BB;
    const float* __restrict__ rowp = acts + (size_t)row * VV;
    const float4* __restrict__ p = (const float4*)rowp;
    const int tid = threadIdx.x;

    if (row == 0 && tid == 0) out[0] = 0.f;        // zero the batch-mean accumulator

    float m = NEGF, s = 0.f;
    #pragma unroll 4
    for (int i = tid; i < VV/4; i += 256) {
        float4 v = p[i];
        float mx = fmaxf(fmaxf(v.x, v.y), fmaxf(v.z, v.w));
        if (mx > m) { s *= __expf(m - mx); m = mx; }
        s += __expf(v.x - m) + __expf(v.y - m) + __expf(v.z - m) + __expf(v.w - m);
    }
    #pragma unroll
    for (int off = 16; off; off >>= 1) {
        float m2 = __shfl_xor_sync(0xffffffffu, m, off);
        float s2 = __shfl_xor_sync(0xffffffffu, s, off);
        float M = fmaxf(m, m2);
        s = s * __expf(m - M) + s2 * __expf(m2 - M);
        m = M;
    }
    __shared__ float sm[8], sv[8];
    __shared__ float sLogZ;
    int w = tid >> 5;
    if ((tid & 31) == 0) { sm[w] = m; sv[w] = s; }
    __syncthreads();
    if (tid == 0) {
        float M = sm[0], Sv = sv[0];
        #pragma unroll
        for (int i = 1; i < 8; i++) {
            float m2 = sm[i], s2 = sv[i];
            float Mn = fmaxf(M, m2);
            Sv = Sv * __expf(M - Mn) + s2 * __expf(m2 - Mn);
            M = Mn;
        }
        sLogZ = M + __logf(Sv);
    }
    __syncthreads();

    // Gather 201 extended-label emissions (L1 hits), scale to log2 domain.
    if (tid < SS) {
        int lab = (tid & 1) ? __ldg(&targets[b*LL + (tid >> 1)]) : 0;
        g_lp[(size_t)row * SS + tid] = (rowp[lab] - sLogZ) * LOG2E;
    }
}

// ---------------------------------------------------------------------------
// K2: alpha scan, TWO time-steps per barrier, register alphas + shfl.
//     Warp w: lanes 4..31 own states 28w..28w+27; lanes 0..3 mirror the
//     previous warp's top 4 states. All lp prefetch slots are COMPILE-TIME
//     indexed (group-unrolled) so they live in registers, not local memory.
// ---------------------------------------------------------------------------
__global__ __launch_bounds__(32*SWARPS) void scan_kernel(const int* __restrict__ targets,
                                                         const int* __restrict__ act_lens,
                                                         const int* __restrict__ label_lens,
                                                         float* __restrict__ out) {
    const int b   = blockIdx.x;
    const int tid = threadIdx.x;
    const int w   = tid >> 5;
    const int l   = tid & 31;
    const int s   = OWN * w + l - 4;           // state id (mirrors for l<4)
    const bool live = (s >= 0 && s < SS);
    const bool owned = (l >= 4) && live;
    const int alen = act_lens[b];

    __shared__ float bnd[2][SWARPS*4];         // boundary states, double-buffered
    __shared__ float fin[SS];

    bool cs = false;                           // can_skip (odd states only)
    if (live && (s & 1)) {
        int cl = targets[b*LL + (s >> 1)];
        int pl = (s >= 3) ? targets[b*LL + ((s - 2) >> 1)] : -1;
        cs = (cl != 0) && (cl != pl);
    }

    // alpha[0]
    float a = NEGF;
    if (live && s <= 1) a = g_lp[(size_t)b * SS + s];

    const int NPAIR = (TT - 2) / 2;            // 255 pairs: t = 1..510

    // lp prefetch: DEPTH pairs, compile-time slots. Pair p covers t=1+2p, 2+2p.
    float ltA[DEPTH], lt1A[DEPTH], ltB[DEPTH], lt1B[DEPTH];
    #pragma unroll
    for (int j = 0; j < DEPTH; j++) {
        int t = 1 + 2*j;
        ltA[j]  = live ? g_lp[(size_t)(t*BB + b)*SS + s]     : 0.f;
        lt1A[j] = live ? g_lp[(size_t)((t+1)*BB + b)*SS + s] : 0.f;
    }
    __syncthreads();

    for (int p0 = 0; p0 < NPAIR; p0 += DEPTH) {
        // prefetch next group (compile-time slot index)
        #pragma unroll
        for (int j = 0; j < DEPTH; j++) {
            int pn = p0 + DEPTH + j;
            bool ok = live && (pn < NPAIR);
            int t = 1 + 2*pn;
            ltB[j]  = ok ? g_lp[(size_t)(t*BB + b)*SS + s]     : 0.f;
            lt1B[j] = ok ? g_lp[(size_t)((t+1)*BB + b)*SS + s] : 0.f;
        }
        #pragma unroll
        for (int j = 0; j < DEPTH; j++) {
            const int p = p0 + j;
            if (p >= NPAIR) break;             // uniform across block
            const int t = 1 + 2*p;
            float lp_t  = ltA[j];
            float lp_t1 = lt1A[j];

            // ---- step A: c = alpha[t][s]  (valid for lanes >= 2)
            float a2 = __shfl_up_sync(0xffffffffu, a, 1);
            float a3 = __shfl_up_sync(0xffffffffu, a, 2);
            float c;
            {
                float a3e = cs ? a3 : NEGF;
                float m = fmaxf(a, fmaxf(a2, a3e));
                float r = ex2f(a - m) + ex2f(a2 - m) + ex2f(a3e - m);
                c = m + lg2f(r) + lp_t;
            }
            c = (t < alen) ? c : a;
            if (!live) c = NEGF;

            // ---- step B: nv = alpha[t+1][s]  (valid for lanes >= 4)
            float c2 = __shfl_up_sync(0xffffffffu, c, 1);
            float c3 = __shfl_up_sync(0xffffffffu, c, 2);
            float nv;
            {
                float c3e = cs ? c3 : NEGF;
                float m = fmaxf(c, fmaxf(c2, c3e));
                float r = ex2f(c - m) + ex2f(c2 - m) + ex2f(c3e - m);
                nv = m + lg2f(r) + lp_t1;
            }
            nv = (t + 1 < alen) ? nv : c;
            if (!live) nv = NEGF;

            // ---- boundary exchange (one barrier per 2 steps); j parity is
            // compile-time, so bnd index is static.
            if (l >= 28) bnd[j & 1][w*4 + (l - 28)] = nv;  // states 28w+24..28w+27
            __syncthreads();
            if (l < 4) a = (w > 0) ? bnd[j & 1][(w - 1)*4 + l] : NEGF;
            else       a = nv;
        }
        #pragma unroll
        for (int j = 0; j < DEPTH; j++) { ltA[j] = ltB[j]; lt1A[j] = lt1B[j]; }
    }

    // ---- tail: single step t = TT-1 = 511
    {
        const int t = TT - 1;
        float lp_t = live ? g_lp[(size_t)(t*BB + b)*SS + s] : 0.f;
        float a2 = __shfl_up_sync(0xffffffffu, a, 1);
        float a3 = __shfl_up_sync(0xffffffffu, a, 2);
        float a3e = cs ? a3 : NEGF;
        float m = fmaxf(a, fmaxf(a2, a3e));
        float r = ex2f(a - m) + ex2f(a2 - m) + ex2f(a3e - m);
        float c = m + lg2f(r) + lp_t;
        a = (t < alen) ? c : a;
    }

    if (owned) fin[s] = a;
    __syncthreads();
    if (tid == 0) {
        int sl = 2 * label_lens[b];
        float x = fin[sl], y = fin[sl - 1];
        float m = fmaxf(x, y);
        float ll2 = m + lg2f(ex2f(x - m) + ex2f(y - m));   // log2 domain
        atomicAdd(out, -ll2 * (LN2 / (float)BB));
    }
}

// ---------------------------------------------------------------------------
extern "C" void kernel_launch(void* const* d_in, const int* in_sizes, int n_in,
                              void* d_out, int out_size) {
    const float* acts       = (const float*)d_in[0];
    const int*   targets    = (const int*)d_in[1];
    const int*   act_lens   = (const int*)d_in[2];
    const int*   label_lens = (const int*)d_in[3];
    float* out = (float*)d_out;

    logz_gather_kernel<<<TT*BB, 256>>>(acts, targets, out);
    scan_kernel<<<BB, 32*SWARPS>>>(targets, act_lens, label_lens, out);
}